// round 5
// baseline (speedup 1.0000x reference)
#include <cuda_runtime.h>
#include <cstdint>
#include <math.h>

typedef unsigned long long ull;

#define NTH 512
#define VP 72          // padded v/r row pitch (floats)
#define VR 36          // v rows per CTA: 32 own + 2 halo each side
#define RROWS 36
#define MROWS 40
#define MP 68

// shared-memory layout (float offsets)
#define OFF_VA  0
#define OFF_VB  2592
#define OFF_R   5184
#define OFF_M   7776                   // ints, 40*68 = 2720
#define OFF_WQP 10496                  // wq splat pairs [25][8][2]
#define OFF_WWP 10896                  // w  splat pairs [25][8][2]
#define OFF_FCP 11296                  // fc splat pairs [8][4][2]
#define OFF_LT  11360                  // LUT[25][4]
#define OFF_WE  11460                  // Weff[2][25] (+pad)
#define OFF_BE  11512
#define OFF_QR  11520                  // qr[8][32][64]
#define SM_FLOATS (OFF_QR + 8*32*64)   // 27904
#define SMEM_BYTES (SM_FLOATS * 4)     // 111616 B

#define FMA2(d,a,b,c) asm("fma.rn.f32x2 %0,%1,%2,%3;" : "=l"(d) : "l"(a), "l"(b), "l"(c))
#define PACK2(d,lo,hi) asm("mov.b64 %0,{%1,%2};" : "=l"(d) : "f"(lo), "f"(hi))
#define UNPK2(lo,hi,s) asm("mov.b64 {%0,%1},%2;" : "=f"(lo), "=f"(hi) : "l"(s))

__device__ __forceinline__ uint32_t smem_u32(const void* p) {
    uint32_t a;
    asm("{ .reg .u64 t; cvta.to.shared.u64 t, %1; cvt.u32.u64 %0, t; }"
        : "=r"(a) : "l"(p));
    return a;
}
__device__ __forceinline__ uint32_t mapa_rank(uint32_t a, uint32_t rk) {
    uint32_t r;
    asm("mapa.shared::cluster.u32 %0, %1, %2;" : "=r"(r) : "r"(a), "r"(rk));
    return r;
}
__device__ __forceinline__ void st_remote_f2(uint32_t a, float x, float y) {
    asm volatile("st.shared::cluster.v2.f32 [%0], {%1,%2};"
                 :: "r"(a), "f"(x), "f"(y) : "memory");
}
#define CSYNC() do { \
    asm volatile("barrier.cluster.arrive.aligned;" ::: "memory"); \
    asm volatile("barrier.cluster.wait.aligned;"   ::: "memory"); } while (0)

// load 6-row sliding-pair window from padded smem plane at (yo, x0)
#define LOAD_WIN(va2, base) do {                                            \
    _Pragma("unroll")                                                       \
    for (int i_ = 0; i_ < 6; i_++) {                                        \
        const ull* rp_ = (const ull*)((base) + (yo + i_) * VP + x0);        \
        ull e0_ = rp_[0], e1_ = rp_[1], e2_ = rp_[2];                       \
        float a1_, a2_, a3_, a4_, t_;                                       \
        UNPK2(t_,  a1_, e0_);                                               \
        UNPK2(a2_, a3_, e1_);                                               \
        UNPK2(a4_, t_,  e2_);                                               \
        va2[i_][0] = e0_; va2[i_][2] = e1_; va2[i_][4] = e2_;               \
        PACK2(va2[i_][1], a1_, a2_);                                        \
        PACK2(va2[i_][3], a3_, a4_);                                        \
    } } while (0)

__global__ void __cluster_dims__(2,1,1) __launch_bounds__(NTH, 1)
vin_kernel(const int*   __restrict__ maze,
           const float* __restrict__ emb,
           const float* __restrict__ encode_w,
           const float* __restrict__ encode_b,
           const float* __restrict__ r_w,
           const float* __restrict__ q_w,
           const float* __restrict__ w,
           const float* __restrict__ fc_w,
           float* __restrict__ out)
{
    extern __shared__ float sm[];
    float* rsm = sm + OFF_R;
    int*   msm = (int*)(sm + OFF_M);
    float* wqP = sm + OFF_WQP;
    float* wwP = sm + OFF_WWP;
    float* fcP = sm + OFF_FCP;
    float* Lt  = sm + OFF_LT;
    float* We  = sm + OFF_WE;
    float* qrs = sm + OFF_QR;

    const int tid  = threadIdx.x;
    const int rank = blockIdx.x;       // 0 = rows 0..31, 1 = rows 32..63
    const int b    = blockIdx.y;
    const int tx   = tid & 31;
    const int ty   = tid >> 5;
    const int x0   = tx * 2;
    const int yo   = ty * 2;
    const int gy0  = rank * 32;

    const uint32_t my32   = smem_u32(sm);
    const uint32_t peer32 = mapa_rank(my32, rank ^ 1);

    // ---------------- prologue ----------------
    for (int i = tid; i < 200; i += NTH) {
        int c = i / 25, t = i - c * 25;
        float qv = q_w[i], wv = w[i];
        wqP[t * 16 + c * 2]     = qv;
        wqP[t * 16 + c * 2 + 1] = qv;
        wwP[t * 16 + c * 2]     = wv;
        wwP[t * 16 + c * 2 + 1] = wv;
    }
    if (tid < 32) {
        int a = tid >> 3, c = tid & 7;
        float f = fc_w[tid];
        fcP[c * 8 + a * 2] = f; fcP[c * 8 + a * 2 + 1] = f;
    }
    if (tid >= 64 && tid < 114) {
        int t = tid - 64;
        float s = 0.f;
        #pragma unroll 5
        for (int c = 0; c < 150; ++c) s += r_w[c] * encode_w[c * 50 + t];
        We[t] = s;
    }
    if (tid == 63) {
        float s = 0.f;
        for (int c = 0; c < 150; ++c) s += r_w[c] * encode_b[c];
        sm[OFF_BE] = s;
    }
    for (int i = tid; i < MROWS * MP; i += NTH) msm[i] = 3;  // sentinel
    for (int i = tid; i < VR * VP; i += NTH) {
        sm[OFF_VA + i] = 0.f; sm[OFF_VB + i] = 0.f; rsm[i] = 0.f;
    }
    __syncthreads();

    if (tid < 75) {
        int t = tid / 3, mv = tid - t * 3;
        Lt[t * 4 + mv] = We[t] * emb[2 * mv] + We[25 + t] * emb[2 * mv + 1];
        if (mv == 0) Lt[t * 4 + 3] = 0.f;
    }
    const int* mz = maze + b * 4096;
    for (int i = tid; i < MROWS * 64; i += NTH) {
        int mr = i >> 6, c = i & 63, g = gy0 - 4 + mr;
        if ((unsigned)g < 64u) msm[mr * MP + c + 2] = mz[g * 64 + c];
    }
    CSYNC();   // local: LUT/maze visible; cluster: peer's v buffers zeroed

    // ---------------- r = LUT-conv(maze) + b_eff ----------------
    {
        const float bv = sm[OFF_BE];
        for (int i = tid; i < RROWS * 64; i += NTH) {
            int vr = i >> 6, c = i & 63, g = gy0 - 2 + vr;
            if ((unsigned)g < 64u) {
                float s = bv;
                #pragma unroll
                for (int dy = 0; dy < 5; dy++)
                    #pragma unroll
                    for (int dx = 0; dx < 5; dx++)
                        s += Lt[(dy * 5 + dx) * 4 + msm[(vr + dy) * MP + c + dx]];
                rsm[vr * VP + c + 2] = s;
            }
        }
    }
    __syncthreads();

    // ---------------- qr = conv(r, wq); v0 = max_c qr ----------------
    {
        ull va2[6][5];
        LOAD_WIN(va2, rsm);
        ull qc2[8][2];
        #pragma unroll
        for (int c = 0; c < 8; c++) { qc2[c][0] = 0ull; qc2[c][1] = 0ull; }
        #pragma unroll
        for (int ky = 0; ky < 5; ky++)
            #pragma unroll
            for (int kx = 0; kx < 5; kx++) {
                const ulonglong2* wp = (const ulonglong2*)(wqP + (ky * 5 + kx) * 16);
                ulonglong2 w01 = wp[0], w23 = wp[1], w45 = wp[2], w67 = wp[3];
                const ull wv[8] = {w01.x, w01.y, w23.x, w23.y,
                                   w45.x, w45.y, w67.x, w67.y};
                #pragma unroll
                for (int c = 0; c < 8; c++) {
                    FMA2(qc2[c][0], wv[c], va2[ky][kx],     qc2[c][0]);
                    FMA2(qc2[c][1], wv[c], va2[ky + 1][kx], qc2[c][1]);
                }
            }
        // store qr + compute v0
        float vn[2][2];
        UNPK2(vn[0][0], vn[0][1], qc2[0][0]);
        UNPK2(vn[1][0], vn[1][1], qc2[0][1]);
        #pragma unroll
        for (int c = 0; c < 8; c++) {
            #pragma unroll
            for (int i = 0; i < 2; i++) {
                *(ull*)(qrs + c * 2048 + (yo + i) * 64 + x0) = qc2[c][i];
                if (c) {
                    float lo, hi;
                    UNPK2(lo, hi, qc2[c][i]);
                    vn[i][0] = fmaxf(vn[i][0], lo);
                    vn[i][1] = fmaxf(vn[i][1], hi);
                }
            }
        }
        #pragma unroll
        for (int i = 0; i < 2; i++)
            *(float2*)(sm + OFF_VA + (yo + 2 + i) * VP + x0 + 2) =
                make_float2(vn[i][0], vn[i][1]);
        if (rank == 0 && ty == 15) {
            #pragma unroll
            for (int i = 0; i < 2; i++)
                st_remote_f2(peer32 + (OFF_VA + i * VP + x0 + 2) * 4, vn[i][0], vn[i][1]);
        }
        if (rank == 1 && ty == 0) {
            #pragma unroll
            for (int i = 0; i < 2; i++)
                st_remote_f2(peer32 + (OFF_VA + (34 + i) * VP + x0 + 2) * 4, vn[i][0], vn[i][1]);
        }
    }
    CSYNC();

    // ---------------- 9 value-iteration steps ----------------
    for (int k = 0; k < 9; ++k) {
        const int inOff  = (k & 1) ? OFF_VB : OFF_VA;
        const int outOff = (k & 1) ? OFF_VA : OFF_VB;
        const float* vin = sm + inOff;
        ull va2[6][5];
        LOAD_WIN(va2, vin);
        ull qc2[8][2];
        #pragma unroll
        for (int c = 0; c < 8; c++) {
            qc2[c][0] = *(const ull*)(qrs + c * 2048 + yo * 64 + x0);
            qc2[c][1] = *(const ull*)(qrs + c * 2048 + (yo + 1) * 64 + x0);
        }
        #pragma unroll
        for (int ky = 0; ky < 5; ky++)
            #pragma unroll
            for (int kx = 0; kx < 5; kx++) {
                const ulonglong2* wp = (const ulonglong2*)(wwP + (ky * 5 + kx) * 16);
                ulonglong2 w01 = wp[0], w23 = wp[1], w45 = wp[2], w67 = wp[3];
                const ull wv[8] = {w01.x, w01.y, w23.x, w23.y,
                                   w45.x, w45.y, w67.x, w67.y};
                #pragma unroll
                for (int c = 0; c < 8; c++) {
                    FMA2(qc2[c][0], wv[c], va2[ky][kx],     qc2[c][0]);
                    FMA2(qc2[c][1], wv[c], va2[ky + 1][kx], qc2[c][1]);
                }
            }
        float vn[2][2];
        UNPK2(vn[0][0], vn[0][1], qc2[0][0]);
        UNPK2(vn[1][0], vn[1][1], qc2[0][1]);
        #pragma unroll
        for (int c = 1; c < 8; c++)
            #pragma unroll
            for (int i = 0; i < 2; i++) {
                float lo, hi;
                UNPK2(lo, hi, qc2[c][i]);
                vn[i][0] = fmaxf(vn[i][0], lo);
                vn[i][1] = fmaxf(vn[i][1], hi);
            }
        #pragma unroll
        for (int i = 0; i < 2; i++)
            *(float2*)(sm + outOff + (yo + 2 + i) * VP + x0 + 2) =
                make_float2(vn[i][0], vn[i][1]);
        if (rank == 0 && ty == 15) {
            #pragma unroll
            for (int i = 0; i < 2; i++)
                st_remote_f2(peer32 + (outOff + i * VP + x0 + 2) * 4, vn[i][0], vn[i][1]);
        }
        if (rank == 1 && ty == 0) {
            #pragma unroll
            for (int i = 0; i < 2; i++)
                st_remote_f2(peer32 + (outOff + (34 + i) * VP + x0 + 2) * 4, vn[i][0], vn[i][1]);
        }
        CSYNC();
    }

    // ---------------- final: q10 = qr + conv(v9,w); out = q10 @ fc^T ----------------
    {
        const float* vin = sm + OFF_VB;   // v9 in buffer B
        ull va2[6][5];
        LOAD_WIN(va2, vin);
        ull oa2[2][4];                    // packed over pixel pair, per action
        #pragma unroll
        for (int i = 0; i < 2; i++)
            #pragma unroll
            for (int a = 0; a < 4; a++) oa2[i][a] = 0ull;
        #pragma unroll
        for (int c = 0; c < 8; c++) {
            ull qc2[2];
            qc2[0] = *(const ull*)(qrs + c * 2048 + yo * 64 + x0);
            qc2[1] = *(const ull*)(qrs + c * 2048 + (yo + 1) * 64 + x0);
            #pragma unroll
            for (int ky = 0; ky < 5; ky++)
                #pragma unroll
                for (int kx = 0; kx < 5; kx++) {
                    ull wv = *(const ull*)(wwP + (ky * 5 + kx) * 16 + c * 2);
                    FMA2(qc2[0], wv, va2[ky][kx],     qc2[0]);
                    FMA2(qc2[1], wv, va2[ky + 1][kx], qc2[1]);
                }
            #pragma unroll
            for (int a = 0; a < 4; a++) {
                ull fv = *(const ull*)(fcP + c * 8 + a * 2);
                FMA2(oa2[0][a], fv, qc2[0], oa2[0][a]);
                FMA2(oa2[1][a], fv, qc2[1], oa2[1][a]);
            }
        }
        float* og = out + (size_t)b * 4096 * 4;
        #pragma unroll
        for (int i = 0; i < 2; i++) {
            float o0[4], o1[4];
            #pragma unroll
            for (int a = 0; a < 4; a++) UNPK2(o0[a], o1[a], oa2[i][a]);
            *(float4*)(og + ((gy0 + yo + i) * 64 + x0) * 4) =
                make_float4(o0[0], o0[1], o0[2], o0[3]);
            *(float4*)(og + ((gy0 + yo + i) * 64 + x0 + 1) * 4) =
                make_float4(o1[0], o1[1], o1[2], o1[3]);
        }
    }
}

extern "C" void kernel_launch(void* const* d_in, const int* in_sizes, int n_in,
                              void* d_out, int out_size) {
    cudaFuncSetAttribute(vin_kernel, cudaFuncAttributeMaxDynamicSharedMemorySize,
                         SMEM_BYTES);
    const int B = in_sizes[0] >> 12;   // maze elements / 4096
    dim3 grid(2, B, 1);
    vin_kernel<<<grid, NTH, SMEM_BYTES>>>(
        (const int*)  d_in[0],  // maze
        (const float*)d_in[1],  // emb
        (const float*)d_in[2],  // encode_w
        (const float*)d_in[3],  // encode_b
        (const float*)d_in[4],  // r_w
        (const float*)d_in[5],  // q_w
        (const float*)d_in[6],  // w
        (const float*)d_in[7],  // fc_w
        (float*)d_out);
}

// round 7
// speedup vs baseline: 1.9390x; 1.9390x over previous
#include <cuda_runtime.h>
#include <cstdint>
#include <math.h>

typedef unsigned long long ull;

#define NTH 512
#define VP 72          // padded v/r row pitch (floats)
#define VR 36          // v rows per CTA: 32 own + 2 halo each side
#define RROWS 36
#define MROWS 40
#define MP 68

// shared-memory layout (float offsets)
#define OFF_VA 0
#define OFF_VB 2592
#define OFF_R  5184
#define OFF_M  7776                    // ints, 40*68 = 2720
#define OFF_WQ 10496                   // wqT[25][8]
#define OFF_WW 10696                   // wwT[25][8]
#define OFF_FC 10896                   // fcT[8][4]
#define OFF_LT 10928                   // LUT[25][4]
#define OFF_WE 11028                   // Weff[2][25] (+pad)
#define OFF_BE 11080
#define OFF_QR 11088                   // qr chan-pair planes: ull[4][32][64] = 16384 floats
#define SM_FLOATS (OFF_QR + 8*32*64)   // 27472
#define SMEM_BYTES (SM_FLOATS * 4)     // 109888 B

#define FMA2(d,a,b,c) asm("fma.rn.f32x2 %0,%1,%2,%3;" : "=l"(d) : "l"(a), "l"(b), "l"(c))
#define PACK2(d,lo,hi) asm("mov.b64 %0,{%1,%2};" : "=l"(d) : "f"(lo), "f"(hi))
#define UNPK2(lo,hi,s) asm("mov.b64 {%0,%1},%2;" : "=f"(lo), "=f"(hi) : "l"(s))

__device__ __forceinline__ uint32_t smem_u32(const void* p) {
    uint32_t a;
    asm("{ .reg .u64 t; cvta.to.shared.u64 t, %1; cvt.u32.u64 %0, t; }"
        : "=r"(a) : "l"(p));
    return a;
}
__device__ __forceinline__ uint32_t mapa_rank(uint32_t a, uint32_t rk) {
    uint32_t r;
    asm("mapa.shared::cluster.u32 %0, %1, %2;" : "=r"(r) : "r"(a), "r"(rk));
    return r;
}
__device__ __forceinline__ void st_remote_f2(uint32_t a, float x, float y) {
    asm volatile("st.shared::cluster.v2.f32 [%0], {%1,%2};"
                 :: "r"(a), "f"(x), "f"(y) : "memory");
}
#define CSYNC() do { \
    asm volatile("barrier.cluster.arrive.aligned;" ::: "memory"); \
    asm volatile("barrier.cluster.wait.aligned;"   ::: "memory"); } while (0)

// Load one padded-plane row (6 cols from (yo+r_, x0)) and splat each value into a ull pair.
#define LOAD_SROW(s_, base_, r_) do {                                     \
    const float* rp_ = (base_) + (yo + (r_)) * VP + x0;                   \
    float2 p0_ = *(const float2*)(rp_);                                   \
    float2 p1_ = *(const float2*)(rp_ + 2);                               \
    float2 p2_ = *(const float2*)(rp_ + 4);                               \
    PACK2(s_[0], p0_.x, p0_.x); PACK2(s_[1], p0_.y, p0_.y);               \
    PACK2(s_[2], p1_.x, p1_.x); PACK2(s_[3], p1_.y, p1_.y);               \
    PACK2(s_[4], p2_.x, p2_.x); PACK2(s_[5], p2_.y, p2_.y);               \
} while (0)

// One tap column sweep for tap-row ky_: rA_ = splat row ky_ (pixel i=0),
// rB_ = splat row ky_+1 (pixel i=1). 16 FMA2 per kx.
#define KY_STEP(ky_, rA_, rB_)                                            \
    _Pragma("unroll")                                                     \
    for (int kx = 0; kx < 5; kx++) {                                      \
        const ulonglong2* wp_ = (const ulonglong2*)(wT + ((ky_)*5 + kx)*8);\
        ulonglong2 wA_ = wp_[0], wB_ = wp_[1];                            \
        FMA2(qc2[0][0][0], wA_.x, rA_[kx],   qc2[0][0][0]);               \
        FMA2(qc2[0][0][1], wA_.x, rA_[kx+1], qc2[0][0][1]);               \
        FMA2(qc2[0][1][0], wA_.x, rB_[kx],   qc2[0][1][0]);               \
        FMA2(qc2[0][1][1], wA_.x, rB_[kx+1], qc2[0][1][1]);               \
        FMA2(qc2[1][0][0], wA_.y, rA_[kx],   qc2[1][0][0]);               \
        FMA2(qc2[1][0][1], wA_.y, rA_[kx+1], qc2[1][0][1]);               \
        FMA2(qc2[1][1][0], wA_.y, rB_[kx],   qc2[1][1][0]);               \
        FMA2(qc2[1][1][1], wA_.y, rB_[kx+1], qc2[1][1][1]);               \
        FMA2(qc2[2][0][0], wB_.x, rA_[kx],   qc2[2][0][0]);               \
        FMA2(qc2[2][0][1], wB_.x, rA_[kx+1], qc2[2][0][1]);               \
        FMA2(qc2[2][1][0], wB_.x, rB_[kx],   qc2[2][1][0]);               \
        FMA2(qc2[2][1][1], wB_.x, rB_[kx+1], qc2[2][1][1]);               \
        FMA2(qc2[3][0][0], wB_.y, rA_[kx],   qc2[3][0][0]);               \
        FMA2(qc2[3][0][1], wB_.y, rA_[kx+1], qc2[3][0][1]);               \
        FMA2(qc2[3][1][0], wB_.y, rB_[kx],   qc2[3][1][0]);               \
        FMA2(qc2[3][1][1], wB_.y, rB_[kx+1], qc2[3][1][1]);               \
    }

// Full 5x5 conv over channel-pair accumulators, rolling 2-row splat ring.
#define CONV_PAIRS(vplane_)                                               \
    do {                                                                  \
        ull s0[6], s1[6];                                                 \
        LOAD_SROW(s0, vplane_, 0);                                        \
        LOAD_SROW(s1, vplane_, 1);                                        \
        KY_STEP(0, s0, s1)                                                \
        LOAD_SROW(s0, vplane_, 2);                                        \
        KY_STEP(1, s1, s0)                                                \
        LOAD_SROW(s1, vplane_, 3);                                        \
        KY_STEP(2, s0, s1)                                                \
        LOAD_SROW(s0, vplane_, 4);                                        \
        KY_STEP(3, s1, s0)                                                \
        LOAD_SROW(s1, vplane_, 5);                                        \
        KY_STEP(4, s0, s1)                                                \
    } while (0)

__global__ void __cluster_dims__(2,1,1) __launch_bounds__(NTH, 1)
vin_kernel(const int*   __restrict__ maze,
           const float* __restrict__ emb,
           const float* __restrict__ encode_w,
           const float* __restrict__ encode_b,
           const float* __restrict__ r_w,
           const float* __restrict__ q_w,
           const float* __restrict__ w,
           const float* __restrict__ fc_w,
           float* __restrict__ out)
{
    extern __shared__ float sm[];
    float* rsm = sm + OFF_R;
    int*   msm = (int*)(sm + OFF_M);
    float* wqT = sm + OFF_WQ;
    float* wwT = sm + OFF_WW;
    float* fcT = sm + OFF_FC;
    float* Lt  = sm + OFF_LT;
    float* We  = sm + OFF_WE;
    ull*   qru = (ull*)(sm + OFF_QR);   // [cp][32][64] channel-pair planes

    const int tid  = threadIdx.x;
    const int rank = blockIdx.x;        // 0 = rows 0..31, 1 = rows 32..63
    const int b    = blockIdx.y;
    const int tx   = tid & 31;
    const int ty   = tid >> 5;
    const int x0   = tx * 2;
    const int yo   = ty * 2;
    const int gy0  = rank * 32;

    const uint32_t my32   = smem_u32(sm);
    const uint32_t peer32 = mapa_rank(my32, rank ^ 1);

    // ---------------- prologue ----------------
    for (int i = tid; i < 200; i += NTH) {
        int c = i / 25, t = i - c * 25;
        wqT[t * 8 + c] = q_w[i];
        wwT[t * 8 + c] = w[i];
    }
    if (tid < 32) { int a = tid >> 3, c = tid & 7; fcT[c * 4 + a] = fc_w[tid]; }
    if (tid >= 64 && tid < 114) {
        int t = tid - 64;
        float s = 0.f;
        #pragma unroll 5
        for (int c = 0; c < 150; ++c) s += r_w[c] * encode_w[c * 50 + t];
        We[t] = s;
    }
    if (tid == 63) {
        float s = 0.f;
        for (int c = 0; c < 150; ++c) s += r_w[c] * encode_b[c];
        sm[OFF_BE] = s;
    }
    for (int i = tid; i < MROWS * MP; i += NTH) msm[i] = 3;  // sentinel
    for (int i = tid; i < VR * VP; i += NTH) {
        sm[OFF_VA + i] = 0.f; sm[OFF_VB + i] = 0.f; rsm[i] = 0.f;
    }
    __syncthreads();

    if (tid < 75) {
        int t = tid / 3, mv = tid - t * 3;
        Lt[t * 4 + mv] = We[t] * emb[2 * mv] + We[25 + t] * emb[2 * mv + 1];
        if (mv == 0) Lt[t * 4 + 3] = 0.f;
    }
    const int* mz = maze + b * 4096;
    for (int i = tid; i < MROWS * 64; i += NTH) {
        int mr = i >> 6, c = i & 63, g = gy0 - 4 + mr;
        if ((unsigned)g < 64u) msm[mr * MP + c + 2] = mz[g * 64 + c];
    }
    CSYNC();   // local: LUT/maze visible; cluster: peer's v buffers zeroed

    // ---------------- r = LUT-conv(maze) + b_eff ----------------
    {
        const float bv = sm[OFF_BE];
        for (int i = tid; i < RROWS * 64; i += NTH) {
            int vr = i >> 6, c = i & 63, g = gy0 - 2 + vr;
            if ((unsigned)g < 64u) {
                float s = bv;
                #pragma unroll
                for (int dy = 0; dy < 5; dy++)
                    #pragma unroll
                    for (int dx = 0; dx < 5; dx++)
                        s += Lt[(dy * 5 + dx) * 4 + msm[(vr + dy) * MP + c + dx]];
                rsm[vr * VP + c + 2] = s;
            }
        }
    }
    __syncthreads();

    // ---------------- qr = conv(r, wq); v0 = max_c qr ----------------
    {
        ull qc2[4][2][2];
        #pragma unroll
        for (int cp = 0; cp < 4; cp++)
            #pragma unroll
            for (int i = 0; i < 2; i++) { qc2[cp][i][0] = 0ull; qc2[cp][i][1] = 0ull; }
        const float* wT = wqT;
        CONV_PAIRS(rsm);
        // store qr + compute v0
        float vn[2][2];
        #pragma unroll
        for (int i = 0; i < 2; i++) {
            #pragma unroll
            for (int cp = 0; cp < 4; cp++) {
                ulonglong2 st; st.x = qc2[cp][i][0]; st.y = qc2[cp][i][1];
                *(ulonglong2*)(qru + cp * 2048 + (yo + i) * 64 + x0) = st;
            }
            #pragma unroll
            for (int j = 0; j < 2; j++) {
                float lo, hi;
                UNPK2(lo, hi, qc2[0][i][j]);
                float m = fmaxf(lo, hi);
                #pragma unroll
                for (int cp = 1; cp < 4; cp++) {
                    UNPK2(lo, hi, qc2[cp][i][j]);
                    m = fmaxf(m, fmaxf(lo, hi));
                }
                vn[i][j] = m;
            }
        }
        #pragma unroll
        for (int i = 0; i < 2; i++)
            *(float2*)(sm + OFF_VA + (yo + 2 + i) * VP + x0 + 2) =
                make_float2(vn[i][0], vn[i][1]);
        if (rank == 0 && ty == 15) {
            #pragma unroll
            for (int i = 0; i < 2; i++)
                st_remote_f2(peer32 + (OFF_VA + i * VP + x0 + 2) * 4, vn[i][0], vn[i][1]);
        }
        if (rank == 1 && ty == 0) {
            #pragma unroll
            for (int i = 0; i < 2; i++)
                st_remote_f2(peer32 + (OFF_VA + (34 + i) * VP + x0 + 2) * 4, vn[i][0], vn[i][1]);
        }
    }
    CSYNC();

    // ---------------- 9 value-iteration steps ----------------
    for (int k = 0; k < 9; ++k) {
        const int inOff  = (k & 1) ? OFF_VB : OFF_VA;
        const int outOff = (k & 1) ? OFF_VA : OFF_VB;
        const float* vin = sm + inOff;
        ull qc2[4][2][2];
        #pragma unroll
        for (int cp = 0; cp < 4; cp++)
            #pragma unroll
            for (int i = 0; i < 2; i++) {
                ulonglong2 ld = *(const ulonglong2*)(qru + cp * 2048 + (yo + i) * 64 + x0);
                qc2[cp][i][0] = ld.x; qc2[cp][i][1] = ld.y;
            }
        const float* wT = wwT;
        CONV_PAIRS(vin);
        float vn[2][2];
        #pragma unroll
        for (int i = 0; i < 2; i++)
            #pragma unroll
            for (int j = 0; j < 2; j++) {
                float lo, hi;
                UNPK2(lo, hi, qc2[0][i][j]);
                float m = fmaxf(lo, hi);
                #pragma unroll
                for (int cp = 1; cp < 4; cp++) {
                    UNPK2(lo, hi, qc2[cp][i][j]);
                    m = fmaxf(m, fmaxf(lo, hi));
                }
                vn[i][j] = m;
            }
        #pragma unroll
        for (int i = 0; i < 2; i++)
            *(float2*)(sm + outOff + (yo + 2 + i) * VP + x0 + 2) =
                make_float2(vn[i][0], vn[i][1]);
        if (rank == 0 && ty == 15) {
            #pragma unroll
            for (int i = 0; i < 2; i++)
                st_remote_f2(peer32 + (outOff + i * VP + x0 + 2) * 4, vn[i][0], vn[i][1]);
        }
        if (rank == 1 && ty == 0) {
            #pragma unroll
            for (int i = 0; i < 2; i++)
                st_remote_f2(peer32 + (outOff + (34 + i) * VP + x0 + 2) * 4, vn[i][0], vn[i][1]);
        }
        CSYNC();
    }

    // ---------------- final: q10 = qr + conv(v9,w); out = q10 @ fc^T ----------------
    {
        const float* vin = sm + OFF_VB;   // v9 in buffer B
        ull qc2[4][2][2];
        #pragma unroll
        for (int cp = 0; cp < 4; cp++)
            #pragma unroll
            for (int i = 0; i < 2; i++) {
                ulonglong2 ld = *(const ulonglong2*)(qru + cp * 2048 + (yo + i) * 64 + x0);
                qc2[cp][i][0] = ld.x; qc2[cp][i][1] = ld.y;
            }
        const float* wT = wwT;
        CONV_PAIRS(vin);
        float4 fr[8];
        #pragma unroll
        for (int c = 0; c < 8; c++) fr[c] = *(const float4*)(fcT + c * 4);
        float* og = out + (size_t)b * 4096 * 4;
        #pragma unroll
        for (int i = 0; i < 2; i++)
            #pragma unroll
            for (int j = 0; j < 2; j++) {
                float q[8];
                #pragma unroll
                for (int cp = 0; cp < 4; cp++)
                    UNPK2(q[2 * cp], q[2 * cp + 1], qc2[cp][i][j]);
                float4 o = make_float4(0.f, 0.f, 0.f, 0.f);
                #pragma unroll
                for (int c = 0; c < 8; c++) {
                    o.x += q[c] * fr[c].x;
                    o.y += q[c] * fr[c].y;
                    o.z += q[c] * fr[c].z;
                    o.w += q[c] * fr[c].w;
                }
                *(float4*)(og + ((gy0 + yo + i) * 64 + x0 + j) * 4) = o;
            }
    }
}

extern "C" void kernel_launch(void* const* d_in, const int* in_sizes, int n_in,
                              void* d_out, int out_size) {
    cudaFuncSetAttribute(vin_kernel, cudaFuncAttributeMaxDynamicSharedMemorySize,
                         SMEM_BYTES);
    const int B = in_sizes[0] >> 12;   // maze elements / 4096
    dim3 grid(2, B, 1);
    vin_kernel<<<grid, NTH, SMEM_BYTES>>>(
        (const int*)  d_in[0],  // maze
        (const float*)d_in[1],  // emb
        (const float*)d_in[2],  // encode_w
        (const float*)d_in[3],  // encode_b
        (const float*)d_in[4],  // r_w
        (const float*)d_in[5],  // q_w
        (const float*)d_in[6],  // w
        (const float*)d_in[7],  // fc_w
        (float*)d_out);
}